// round 10
// baseline (speedup 1.0000x reference)
#include <cuda_runtime.h>
#include <cuda_bf16.h>

// Fixed problem shapes
#define N_C 500000
#define N_F 2000000
#define KNBR 8
#define ROWW (KNBR + 2)   // 8 neighbor cols + pad + count
#define TPB 256

// Scratch: d = input - pred, padded to float4 (16B-aligned single-sector gathers).
__device__ float4 g_d[N_C + N_F];
__device__ double g_acc;
__device__ unsigned int g_done;

// ---------------------------------------------------------------------------
// Kernel 1: d = input - pred for both meshes (float4 loads + smem transpose).
// Also resets accumulator/done-counter (runs fully before the loss kernels).
// ---------------------------------------------------------------------------
__global__ void diff_kernel(const float* __restrict__ ci,
                            const float* __restrict__ cp,
                            const float* __restrict__ fi,
                            const float* __restrict__ fp,
                            int nc, int nf, int cbd) {
    const int t = threadIdx.x;
    const int b = blockIdx.x;
    if (b == 0 && t == 0) { g_acc = 0.0; g_done = 0u; }

    const float* __restrict__ a;
    const float* __restrict__ p;
    int n, segbase, v0;
    if (b < cbd) { a = ci; p = cp; n = nc; segbase = 0;  v0 = b * TPB; }
    else         { a = fi; p = fp; n = nf; segbase = nc; v0 = (b - cbd) * TPB; }

    __shared__ float s[3 * TPB];

    if (v0 + TPB <= n) {
        // Full block: 256 vertices = 768 floats = 192 float4 per array.
        const int f4base = (v0 >> 2) * 3;  // exact: v0 % 4 == 0
        if (t < 3 * TPB / 4) {
            float4 av = __ldcs((const float4*)a + f4base + t);
            float4 pv = __ldcs((const float4*)p + f4base + t);
            ((float4*)s)[t] = make_float4(av.x - pv.x, av.y - pv.y,
                                          av.z - pv.z, av.w - pv.w);
        }
        __syncthreads();
        // stride-3 smem reads: gcd(3,32)=1 -> conflict-free
        g_d[segbase + v0 + t] =
            make_float4(s[3 * t], s[3 * t + 1], s[3 * t + 2], 0.0f);
    } else {
        const int i = v0 + t;
        if (i < n) {
            const int b3 = 3 * i;
            g_d[segbase + i] = make_float4(a[b3 + 0] - p[b3 + 0],
                                           a[b3 + 1] - p[b3 + 1],
                                           a[b3 + 2] - p[b3 + 2], 0.0f);
        }
    }
}

// ---------------------------------------------------------------------------
// Loss kernel (one mesh per launch, R1-style scalar idx loads):
//   e = d[i] - (sum_valid d[idx[j]]) / count ;  v = ||e||^2
//   block-reduce -> atomicAdd(double, scaled).
// The block that takes the done-counter to total_blocks (necessarily in the
// second, fine launch: stream order) writes the final result.
// ---------------------------------------------------------------------------
__global__ void loss_kernel(const int* __restrict__ lap, int n, int base,
                            double scale, unsigned int total_blocks,
                            float* __restrict__ out) {
    const int i = blockIdx.x * TPB + threadIdx.x;
    float v = 0.0f;
    if (i < n) {
        const float4* __restrict__ d = g_d + base;
        const float4 di = d[i];
        const int* __restrict__ row = lap + (size_t)i * ROWW;

        int idx[KNBR];
#pragma unroll
        for (int j = 0; j < KNBR; j++) idx[j] = row[j];
        const int cnt = row[KNBR + 1];

        float sx = 0.0f, sy = 0.0f, sz = 0.0f;
#pragma unroll
        for (int j = 0; j < KNBR; j++) {
            const int id = idx[j];
            if (id >= 0) {
                const float4 nv = d[id];
                sx += nv.x; sy += nv.y; sz += nv.z;
            }
        }
        const float inv = 1.0f / (float)cnt;
        const float ex = di.x - sx * inv;
        const float ey = di.y - sy * inv;
        const float ez = di.z - sz * inv;
        v = ex * ex + ey * ey + ez * ez;
    }

    // intra-block reduction
#pragma unroll
    for (int off = 16; off > 0; off >>= 1)
        v += __shfl_down_sync(0xFFFFFFFFu, v, off);

    __shared__ float warp_sums[TPB / 32];
    __shared__ bool is_last;
    const int lane = threadIdx.x & 31;
    const int wid  = threadIdx.x >> 5;
    if (lane == 0) warp_sums[wid] = v;
    __syncthreads();

    if (wid == 0) {
        float s = (lane < (TPB >> 5)) ? warp_sums[lane] : 0.0f;
#pragma unroll
        for (int off = 4; off > 0; off >>= 1)
            s += __shfl_down_sync(0xFFFFFFFFu, s, off);
        if (lane == 0) {
            atomicAdd(&g_acc, (double)s * scale);
            __threadfence();
            unsigned int old = atomicAdd(&g_done, 1u);
            is_last = (old == total_blocks - 1u);
        }
    }
    __syncthreads();

    if (is_last && threadIdx.x == 0) {
        __threadfence();
        out[0] = (float)g_acc;
    }
}

extern "C" void kernel_launch(void* const* d_in, const int* in_sizes, int n_in,
                              void* d_out, int out_size) {
    const float* ci = (const float*)d_in[0];  // coarse_input  (N_C,3)
    const float* cp = (const float*)d_in[1];  // coarse_pred   (N_C,3)
    const float* fi = (const float*)d_in[2];  // fine_input    (N_F,3)
    const float* fp = (const float*)d_in[3];  // fine_pred     (N_F,3)
    const int* lic  = (const int*)d_in[4];    // lap_idx_coarse (N_C,10)
    const int* lif  = (const int*)d_in[5];    // lap_idx_fine   (N_F,10)

    const int nc = in_sizes[0] / 3;
    const int nf = in_sizes[2] / 3;

    const int cb = (nc + TPB - 1) / TPB;
    const int fb = (nf + TPB - 1) / TPB;
    const unsigned int total = (unsigned int)(cb + fb);

    diff_kernel<<<cb + fb, TPB>>>(ci, cp, fi, fp, nc, nf, cb);
    loss_kernel<<<cb, TPB>>>(lic, nc, 0,  0.5 / (double)nc, total, (float*)d_out);
    loss_kernel<<<fb, TPB>>>(lif, nf, nc, 0.5 / (double)nf, total, (float*)d_out);
}